// round 16
// baseline (speedup 1.0000x reference)
#include <cuda_runtime.h>
#include <math.h>

// Problem constants (fixed by reference)
#define VOCAB 100000
#define DIM   128
#define BATCH 16384
#define CTX   10
#define NEG   5

#define WARPS_PER_BLOCK 8
#define THREADS (WARPS_PER_BLOCK * 32)
#define ELEMS_PER_WARP 2
#define NUM_BLOCKS (BATCH / (WARPS_PER_BLOCK * ELEMS_PER_WARP))   // 1024

// Scratch (no cudaMalloc allowed)
__device__ double       g_accum  = 0.0;
__device__ unsigned int g_ticket = 0;

__device__ __forceinline__ float log_sigmoid(float x) {
    // stable: min(x,0) - log1p(exp(-|x|))
    return fminf(x, 0.0f) - log1pf(expf(-fabsf(x)));
}

// Asymmetric L2 policy (measured-best): pin u-table, stream w-table.
__device__ __forceinline__ unsigned long long make_policy_keep() {
    unsigned long long pol;
    asm("createpolicy.fractional.L2::evict_last.b64 %0, 1.0;" : "=l"(pol));
    return pol;
}
__device__ __forceinline__ unsigned long long make_policy_stream() {
    unsigned long long pol;
    asm("createpolicy.fractional.L2::evict_first.b64 %0, 1.0;" : "=l"(pol));
    return pol;
}
__device__ __forceinline__ float4 ldg_cg_pol(const float4* p, unsigned long long pol) {
    float4 v;
    asm("ld.global.cg.L2::cache_hint.v4.f32 {%0,%1,%2,%3}, [%4], %5;"
        : "=f"(v.x), "=f"(v.y), "=f"(v.z), "=f"(v.w)
        : "l"(p), "l"(pol));
    return v;
}

// Warp-cooperative L2 prefetch of ALL 16 rows (64 x 128B lines) of element b.
// No registers held, no scoreboard: purely warms L2 under the current work.
__device__ __forceinline__ void prefetch_elem(
    int b, int lane,
    const int* __restrict__ pos_u, const int* __restrict__ pos_w,
    const int* __restrict__ neg_w,
    const float* __restrict__ u_wf, const float* __restrict__ w_wf)
{
    // lanes 0..9: ctx rows; lane 10: pos row; lanes 11..15: neg rows
    int rowidx = 0;
    if (lane < CTX)            rowidx = __ldg(pos_u + b * CTX + lane);
    else if (lane == CTX)      rowidx = __ldg(pos_w + b);
    else if (lane < 16)        rowidx = __ldg(neg_w + b * NEG + (lane - 11));

    #pragma unroll
    for (int t = 0; t < 2; ++t) {
        int j = 2 * lane + t;            // flat line id 0..63
        int r = j >> 2;                  // row 0..15
        int lo = j & 3;                  // 128B line within the 512B row
        int idx = __shfl_sync(0xFFFFFFFFu, rowidx, r);
        const float* base = (r < CTX) ? u_wf : w_wf;
        const float* addr = base + (size_t)idx * DIM + lo * 32;
        asm volatile("prefetch.global.L2 [%0];" :: "l"(addr));
    }
}

__global__ __launch_bounds__(THREADS)
void cbow_loss_fused(const int* __restrict__ pos_u,   // [B, CTX]
                     const int* __restrict__ pos_w,   // [B]
                     const int* __restrict__ neg_w,   // [B, NEG]
                     const float4* __restrict__ u_w,  // [VOCAB, 32] as float4
                     const float4* __restrict__ w_w,  // [VOCAB, 32] as float4
                     float* __restrict__ out)
{
    const int warp = threadIdx.x >> 5;
    const int lane = threadIdx.x & 31;
    const int b0 = (blockIdx.x * WARPS_PER_BLOCK + warp) * ELEMS_PER_WARP;

    const unsigned long long pol_keep   = make_policy_keep();
    const unsigned long long pol_stream = make_policy_stream();
    const float* u_wf = (const float*)u_w;
    const float* w_wf = (const float*)w_w;

    float ls = 0.0f;   // lane0 accumulates logsigmoid terms

    // Prefetch element 2's rows into L2 before starting element 1.
    prefetch_elem(b0 + 1, lane, pos_u, pos_w, neg_w, u_wf, w_wf);

    #pragma unroll
    for (int e = 0; e < ELEMS_PER_WARP; ++e) {
        const int b = b0 + e;

        // --- gather-sum context embeddings (u-table: keep, L2-only) ---
        float4 usum = make_float4(0.f, 0.f, 0.f, 0.f);
        const int* pu = pos_u + b * CTX;
        #pragma unroll
        for (int c = 0; c < CTX; ++c) {
            int idx = __ldg(pu + c);                     // uniform across warp
            float4 v = ldg_cg_pol(u_w + (size_t)idx * 32 + lane, pol_keep);
            usum.x += v.x; usum.y += v.y; usum.z += v.z; usum.w += v.w;
        }

        // --- positive target row (w-table: stream, L2-only) ---
        int pidx = __ldg(pos_w + b);
        float4 p = ldg_cg_pol(w_w + (size_t)pidx * 32 + lane, pol_stream);
        float pd = usum.x * p.x + usum.y * p.y + usum.z * p.z + usum.w * p.w;

        // --- negative rows summed first (dot distributes over the sum) ---
        float4 nsum = make_float4(0.f, 0.f, 0.f, 0.f);
        const int* nw = neg_w + b * NEG;
        #pragma unroll
        for (int k = 0; k < NEG; ++k) {
            int idx = __ldg(nw + k);
            float4 v = ldg_cg_pol(w_w + (size_t)idx * 32 + lane, pol_stream);
            nsum.x += v.x; nsum.y += v.y; nsum.z += v.z; nsum.w += v.w;
        }
        float nd = usum.x * nsum.x + usum.y * nsum.y + usum.z * nsum.z + usum.w * nsum.w;

        // --- warp reduce both dots together ---
        #pragma unroll
        for (int off = 16; off > 0; off >>= 1) {
            pd += __shfl_xor_sync(0xFFFFFFFFu, pd, off);
            nd += __shfl_xor_sync(0xFFFFFFFFu, nd, off);
        }
        if (lane == 0)
            ls += log_sigmoid(pd) + log_sigmoid(-nd);
    }

    __shared__ float s_part[WARPS_PER_BLOCK];
    if (lane == 0)
        s_part[warp] = ls;
    __syncthreads();

    // --- featherweight epilogue: one double atomic per block + ticket ---
    if (threadIdx.x == 0) {
        float acc = 0.f;
        #pragma unroll
        for (int i = 0; i < WARPS_PER_BLOCK; ++i) acc += s_part[i];
        atomicAdd(&g_accum, (double)acc);   // order-insensitive in double
        __threadfence();                    // release before ticket
        unsigned int t = atomicAdd(&g_ticket, 1u);
        if (t == NUM_BLOCKS - 1) {
            __threadfence();                // acquire after last ticket
            double total = g_accum;
            out[0] = (float)(-total);       // loss = -(sum of logsigmoids)
            g_accum  = 0.0;                 // reset for next graph replay
            g_ticket = 0;
        }
    }
}

extern "C" void kernel_launch(void* const* d_in, const int* in_sizes, int n_in,
                              void* d_out, int out_size) {
    const int*    pos_u = (const int*)d_in[0];
    const int*    pos_w = (const int*)d_in[1];
    const int*    neg_w = (const int*)d_in[2];
    const float4* u_w   = (const float4*)d_in[3];
    const float4* w_w   = (const float4*)d_in[4];
    float* out = (float*)d_out;

    cbow_loss_fused<<<NUM_BLOCKS, THREADS>>>(pos_u, pos_w, neg_w, u_w, w_w, out);
}

// round 17
// speedup vs baseline: 1.2429x; 1.2429x over previous
#include <cuda_runtime.h>
#include <math.h>

// Problem constants (fixed by reference)
#define VOCAB 100000
#define DIM   128
#define BATCH 16384
#define CTX   10
#define NEG   5

#define WARPS_PER_BLOCK 8
#define THREADS (WARPS_PER_BLOCK * 32)
#define NUM_BLOCKS (BATCH / WARPS_PER_BLOCK)   // 2048: one element per warp

// Scratch (no cudaMalloc allowed)
__device__ double       g_accum  = 0.0;
__device__ unsigned int g_ticket = 0;

__device__ __forceinline__ float log_sigmoid(float x) {
    // stable: min(x,0) - log1p(exp(-|x|))
    return fminf(x, 0.0f) - log1pf(expf(-fabsf(x)));
}

// Asymmetric L2 policy (measured-best): pin u-table, stream w-table.
__device__ __forceinline__ unsigned long long make_policy_keep() {
    unsigned long long pol;
    asm("createpolicy.fractional.L2::evict_last.b64 %0, 1.0;" : "=l"(pol));
    return pol;
}
__device__ __forceinline__ unsigned long long make_policy_stream() {
    unsigned long long pol;
    asm("createpolicy.fractional.L2::evict_first.b64 %0, 1.0;" : "=l"(pol));
    return pol;
}
__device__ __forceinline__ float4 ldg_cg_pol(const float4* p, unsigned long long pol) {
    float4 v;
    asm("ld.global.cg.L2::cache_hint.v4.f32 {%0,%1,%2,%3}, [%4], %5;"
        : "=f"(v.x), "=f"(v.y), "=f"(v.z), "=f"(v.w)
        : "l"(p), "l"(pol));
    return v;
}

__global__ __launch_bounds__(THREADS)
void cbow_loss_fused(const int* __restrict__ pos_u,   // [B, CTX]
                     const int* __restrict__ pos_w,   // [B]
                     const int* __restrict__ neg_w,   // [B, NEG]
                     const float4* __restrict__ u_w,  // [VOCAB, 32] as float4
                     const float4* __restrict__ w_w,  // [VOCAB, 32] as float4
                     float* __restrict__ out)
{
    const int warp = threadIdx.x >> 5;
    const int lane = threadIdx.x & 31;
    const int b = blockIdx.x * WARPS_PER_BLOCK + warp;   // one element per warp

    const unsigned long long pol_keep   = make_policy_keep();
    const unsigned long long pol_stream = make_policy_stream();

    // --- gather-sum context embeddings (u-table: keep, L2-only) ---
    float4 usum = make_float4(0.f, 0.f, 0.f, 0.f);
    const int* pu = pos_u + b * CTX;
    #pragma unroll
    for (int c = 0; c < CTX; ++c) {
        int idx = __ldg(pu + c);                     // uniform across warp
        float4 v = ldg_cg_pol(u_w + (size_t)idx * 32 + lane, pol_keep);
        usum.x += v.x; usum.y += v.y; usum.z += v.z; usum.w += v.w;
    }

    // --- positive target row (w-table: stream, L2-only) ---
    int pidx = __ldg(pos_w + b);
    float4 p = ldg_cg_pol(w_w + (size_t)pidx * 32 + lane, pol_stream);
    float pd = usum.x * p.x + usum.y * p.y + usum.z * p.z + usum.w * p.w;

    // --- negative rows summed first (dot distributes over the sum) ---
    float4 nsum = make_float4(0.f, 0.f, 0.f, 0.f);
    const int* nw = neg_w + b * NEG;
    #pragma unroll
    for (int k = 0; k < NEG; ++k) {
        int idx = __ldg(nw + k);
        float4 v = ldg_cg_pol(w_w + (size_t)idx * 32 + lane, pol_stream);
        nsum.x += v.x; nsum.y += v.y; nsum.z += v.z; nsum.w += v.w;
    }
    float nd = usum.x * nsum.x + usum.y * nsum.y + usum.z * nsum.z + usum.w * nsum.w;

    // --- warp reduce both dots together ---
    #pragma unroll
    for (int off = 16; off > 0; off >>= 1) {
        pd += __shfl_xor_sync(0xFFFFFFFFu, pd, off);
        nd += __shfl_xor_sync(0xFFFFFFFFu, nd, off);
    }

    __shared__ float s_part[WARPS_PER_BLOCK];
    if (lane == 0)
        s_part[warp] = log_sigmoid(pd) + log_sigmoid(-nd);
    __syncthreads();

    // --- featherweight epilogue: one double atomic per block + ticket ---
    if (threadIdx.x == 0) {
        float acc = 0.f;
        #pragma unroll
        for (int i = 0; i < WARPS_PER_BLOCK; ++i) acc += s_part[i];
        atomicAdd(&g_accum, (double)acc);   // order-insensitive in double
        __threadfence();                    // release before ticket
        unsigned int t = atomicAdd(&g_ticket, 1u);
        if (t == NUM_BLOCKS - 1) {
            __threadfence();                // acquire after last ticket
            double total = g_accum;
            out[0] = (float)(-total);       // loss = -(sum of logsigmoids)
            g_accum  = 0.0;                 // reset for next graph replay
            g_ticket = 0;
        }
    }
}

extern "C" void kernel_launch(void* const* d_in, const int* in_sizes, int n_in,
                              void* d_out, int out_size) {
    const int*    pos_u = (const int*)d_in[0];
    const int*    pos_w = (const int*)d_in[1];
    const int*    neg_w = (const int*)d_in[2];
    const float4* u_w   = (const float4*)d_in[3];
    const float4* w_w   = (const float4*)d_in[4];
    float* out = (float*)d_out;

    cbow_loss_fused<<<NUM_BLOCKS, THREADS>>>(pos_u, pos_w, neg_w, u_w, w_w, out);
}